// round 11
// baseline (speedup 1.0000x reference)
#include <cuda_runtime.h>
#include <cuda_bf16.h>
#include <math.h>
#include <stdint.h>

// ---------------- constants ----------------
#define S_   16
#define N_   256
#define D_   128
#define RR   49
#define K1   2401            // 49*49
#define KPAD 2416            // padded K for GEMM1 (mult of 16)
#define ROWS_T 12288         // 3 levels * 16 * 256
#define MT_G 768             // global m-tiles (12288/16)

// fmapT offsets
#define FT1_OFF 6291456      // 16*48*64*128
#define FT2_OFF 7864320      // + 16*24*32*128

// ---------------- scratch (static device memory; no allocs) ----------------
__device__ float g_fmapT[8257536];           // all 3 transposed fmaps
__device__ float g_vol[ROWS_T * KPAD];       // perm A-layout: [302 kt][768 mt][128]
__device__ float g_h[ROWS_T * 384];          // perm A-layout: [48 kt][768 mt][128]
__device__ float g_emb[ROWS_T * 256];
__device__ float g_w1r[KPAD * 384];          // perm B-layout: [302 kt][48 nt][64]
__device__ float g_w2r[384 * 256];           // perm B-layout: [48 kt][32 nt][64]

// ---------------- helpers ----------------
__device__ __forceinline__ uint32_t f2tf32(float f)
{
    uint32_t r;
    asm("cvt.rna.tf32.f32 %0, %1;" : "=r"(r) : "f"(f));
    return r;
}

__device__ __forceinline__ float tf32r(float f) { return __uint_as_float(f2tf32(f)); }

__device__ __forceinline__ void mma_tf32(float* c, const uint32_t* a, const uint32_t* b)
{
    asm volatile(
        "mma.sync.aligned.m16n8k8.row.col.f32.tf32.tf32.f32 "
        "{%0,%1,%2,%3}, {%4,%5,%6,%7}, {%8,%9}, {%0,%1,%2,%3};"
        : "+f"(c[0]), "+f"(c[1]), "+f"(c[2]), "+f"(c[3])
        : "r"(a[0]), "r"(a[1]), "r"(a[2]), "r"(a[3]), "r"(b[0]), "r"(b[1]));
}

__device__ __forceinline__ void cpa16(uint32_t dst, const void* src)
{
    asm volatile("cp.async.ca.shared.global [%0], [%1], 16;"
                 :: "r"(dst), "l"(src) : "memory");
}
__device__ __forceinline__ void cpa_commit() { asm volatile("cp.async.commit_group;" ::: "memory"); }
__device__ __forceinline__ void cpa_wait0()  { asm volatile("cp.async.wait_group 0;" ::: "memory"); }
__device__ __forceinline__ void cpa_wait1()  { asm volatile("cp.async.wait_group 1;" ::: "memory"); }
__device__ __forceinline__ void cpa_wait2()  { asm volatile("cp.async.wait_group 2;" ::: "memory"); }

// perm A-layout address (element (m,k), MT global m-tiles)
__device__ __forceinline__ size_t aperm(int m, int k, int MT)
{
    return ((size_t)(k >> 3) * MT + (m >> 4)) * 128
         + ((k & 3) * 8 + (m & 7)) * 4 + ((k & 4) >> 1) + ((m & 8) >> 3);
}
// perm B-layout address (element (k,n), NT n-tiles)
__device__ __forceinline__ size_t bperm(int k, int n, int NT)
{
    return ((size_t)(k >> 3) * NT + (n >> 3)) * 64
         + ((k & 3) * 8 + (n & 7)) * 2 + ((k & 4) >> 2);
}

// ---------------- fused transpose [S,D,H,W] -> [S,H*W,D], all 3 levels -------
__global__ void transpose_all_kernel(const float* __restrict__ fm0,
                                     const float* __restrict__ fm1,
                                     const float* __restrict__ fm2,
                                     float* __restrict__ dstBase)
{
    __shared__ float tile[32][33];
    int bx = blockIdx.x;
    const float* src;
    float* dst;
    int HW;
    if (bx < 96)       { src = fm0; dst = dstBase;           HW = 3072; }
    else if (bx < 120) { src = fm1; dst = dstBase + FT1_OFF; HW = 768;  bx -= 96; }
    else               { src = fm2; dst = dstBase + FT2_OFF; HW = 192;  bx -= 120; }

    int s   = blockIdx.z;
    int hw0 = bx * 32;
    int d0  = blockIdx.y * 32;
    int tx  = threadIdx.x;
    for (int i = threadIdx.y; i < 32; i += 8)
        tile[i][tx] = src[(size_t)(s * D_ + d0 + i) * HW + hw0 + tx];
    __syncthreads();
    for (int i = threadIdx.y; i < 32; i += 8)
        dst[(size_t)(s * HW + hw0 + i) * D_ + d0 + tx] = tile[tx][i];
}

// ---------------- pack weights: tf32 round + permute to B-layout ------------
__global__ void pack_weights_kernel(const float* __restrict__ W1s, float* __restrict__ w1d,
                                    const float* __restrict__ W2s, float* __restrict__ w2d)
{
    const int N1 = KPAD * 384;
    int i = blockIdx.x * 256 + threadIdx.x;
    if (i < N1) {
        const int k = i / 384, n = i - k * 384;
        const float v = (k < K1) ? tf32r(W1s[k * 384 + n]) : 0.f;
        w1d[bperm(k, n, 48)] = v;
    } else {
        int j = i - N1;
        if (j < 384 * 256) {
            const int k = j / 256, n = j - k * 256;
            w2d[bperm(k, n, 32)] = tf32r(W2s[k * 256 + n]);
        }
    }
}

// ---------------- vol kernel: per-(s,n,lev) block, 8x8 patch -> mma -> bilinear
#define VAW 132
#define VA_SZ (64 * VAW)    // 8448 floats
#define VB_SZ (56 * VAW)    // 7392 floats
#define VOL_SMEM ((VA_SZ + VB_SZ) * 4)   // 63360 B

__global__ __launch_bounds__(256)
void vol_kernel(const float* __restrict__ fmTbase,
                const float* __restrict__ tf0,
                const float* __restrict__ tf1,
                const float* __restrict__ tf2,
                const float* __restrict__ coords, float* __restrict__ vol)
{
    extern __shared__ float smv[];
    float* As = smv;            // [64][132]
    float* Bs = smv + VA_SZ;    // [56][132]

    const int n = blockIdx.x, s = blockIdx.y, lev = blockIdx.z;
    const int tid = threadIdx.x, lane = tid & 31, wp = tid >> 5;

    int H, W, off;
    float invscale;
    const float* tfs;
    if (lev == 0)      { H = 48; W = 64; off = 0;       invscale = 1.0f;  tfs = tf0; }
    else if (lev == 1) { H = 24; W = 32; off = FT1_OFF; invscale = 0.5f;  tfs = tf1; }
    else               { H = 12; W = 16; off = FT2_OFF; invscale = 0.25f; tfs = tf2; }

    const int sn = s * N_ + n;
    const float cx = coords[sn * 2 + 0] * invscale;
    const float cy = coords[sn * 2 + 1] * invscale;
    const float fxx = floorf(cx), fyy = floorf(cy);
    const int   ix0 = (int)fxx,   iy0 = (int)fyy;
    const float fx = cx - fxx,    fy = cy - fyy;
    const float w00 = (1.f - fx) * (1.f - fy);
    const float w01 = fx * (1.f - fy);
    const float w10 = (1.f - fx) * fy;
    const float w11 = fx * fy;
    const float* base = fmTbase + off + (size_t)s * H * W * D_;

    // gather raw 8x8 texel patch: warp per texel row m; lane owns 4 channels
    #pragma unroll
    for (int m = wp; m < 64; m += 8) {
        const int ty = m >> 3, tx = m & 7;
        const int yy = iy0 + ty - 3, xx = ix0 + tx - 3;
        float4 t = make_float4(0.f, 0.f, 0.f, 0.f);
        if ((yy >= 0) && (yy < H) && (xx >= 0) && (xx < W))
            t = *(const float4*)(base + ((long)yy * W + xx) * D_ + 4 * lane);
        *(float4*)&As[m * VAW + 4 * lane] =
            make_float4(tf32r(t.x), tf32r(t.y), tf32r(t.z), tf32r(t.w));
    }
    // gather tf: warp per ij; lane owns 4 channels
    for (int ij = wp; ij < RR; ij += 8) {
        float4 t = *(const float4*)(tfs + ((long)ij * N_ + n) * D_ + 4 * lane);
        *(float4*)&Bs[ij * VAW + 4 * lane] =
            make_float4(tf32r(t.x), tf32r(t.y), tf32r(t.z), tf32r(t.w));
    }
    __syncthreads();

    const int mrow = lev * 4096 + sn;   // global gemm m-row of this vol row
    if (tid < KPAD - K1) vol[aperm(mrow, K1 + tid, MT_G)] = 0.f;

    // mma: warp -> m tile (warp&3)*16, n half (warp>>2); C = texels . tf
    const int wm  = (wp & 3) * 16;
    const int nh  = wp >> 2;
    const int nt0 = nh ? 4 : 0;
    const int ntN = nh ? 3 : 4;
    const int t = lane & 3, g = lane >> 2;
    const uint32_t* Au = (const uint32_t*)As;
    const uint32_t* Bu = (const uint32_t*)Bs;

    float acc[4][4];
    #pragma unroll
    for (int i = 0; i < 4; i++)
        #pragma unroll
        for (int q = 0; q < 4; q++) acc[i][q] = 0.f;

    #pragma unroll
    for (int kb = 0; kb < 16; kb++) {
        const int kc = kb * 8 + t;
        uint32_t a[4];
        const int ra = (wm + g) * VAW + kc;
        const int rb = (wm + g + 8) * VAW + kc;
        a[0] = Au[ra];     a[1] = Au[rb];
        a[2] = Au[ra + 4]; a[3] = Au[rb + 4];
        #pragma unroll
        for (int ni = 0; ni < 4; ni++) {
            if (ni >= ntN) break;
            const int nb = ((nt0 + ni) * 8 + g) * VAW + kc;
            uint32_t b[2];
            b[0] = Bu[nb]; b[1] = Bu[nb + 4];
            mma_tf32(acc[ni], a, b);
        }
    }

    // store C to smem (reuse region), then bilinear-combine in output space
    __syncthreads();
    float* Cs = smv;    // [64][56]
    #pragma unroll
    for (int ni = 0; ni < 4; ni++) {
        if (ni >= ntN) break;
        const int col0 = (nt0 + ni) * 8 + 2 * t;
        *(float2*)&Cs[(wm + g) * 56 + col0]     = make_float2(acc[ni][0], acc[ni][1]);
        *(float2*)&Cs[(wm + g + 8) * 56 + col0] = make_float2(acc[ni][2], acc[ni][3]);
    }
    __syncthreads();

    for (int idx = tid; idx < K1; idx += 256) {
        const int hw = idx / 49, ij = idx - hw * 49;
        const int h = hw / 7,  w = hw - h * 7;
        const int m00 = h * 8 + w;
        const float v = w00 * Cs[m00 * 56 + ij]
                      + w01 * Cs[(m00 + 1) * 56 + ij]
                      + w10 * Cs[(m00 + 8) * 56 + ij]
                      + w11 * Cs[(m00 + 9) * 56 + ij];
        vol[aperm(mrow, idx, MT_G)] = tf32r(v);
    }
}

// ---------------- 3-stage tf32 GEMM on perm layouts, 128x128, 256 thr -------
__device__ __forceinline__ float gelu_exact(float v)
{
    return 0.5f * v * (1.f + erff(v * 0.7071067811865475f));
}

#define GEMM_SMEM (6 * 512 * 16)   // 49152 B: 3 A-stages + 3 B-stages of 8KB

template <bool GELU, bool ROUND_OUT, bool PERM_OUT>
__global__ __launch_bounds__(256, 2)
void tf32_gemm_perm(const float4* __restrict__ A4, int MT,
                    const float4* __restrict__ B4, int NT,
                    const float* __restrict__ bias,
                    float* __restrict__ C, int ldc,
                    int K)
{
    extern __shared__ float4 smg4[];   // [3][512] A, then [3][512] B

    const int tid  = threadIdx.x;
    const int lane = tid & 31;
    const int warp = tid >> 5;              // 0..7
    const int m0t = blockIdx.y * 8;         // base m-tile (128 rows)
    const int n0  = blockIdx.x * 128;
    const int n0t = n0 >> 3;
    const int wmt = (warp >> 2) * 4;        // warp m-tile offset
    const int wn  = (warp & 3) * 32;
    const int t = lane & 3, g = lane >> 2;

    const uint32_t smBase = (uint32_t)__cvta_generic_to_shared(smg4);

    auto prefetch = [&](int it, int st) {
        const int kt0 = it * 2;
        #pragma unroll
        for (int q = 0; q < 2; q++) {
            const int idx = tid + q * 256;
            const int kt = idx >> 8, rem = idx & 255;
            {   // A: 2 kt x 8 mtiles x 32 lanes of float4
                const int mtile = rem >> 5, ln = rem & 31;
                const float4* src = A4 + ((size_t)(kt0 + kt) * MT + m0t + mtile) * 32 + ln;
                cpa16(smBase + (uint32_t)(st * 512 + idx) * 16, src);
            }
            {   // B: 2 kt x 16 ntiles x 16 float4
                const int ntile = rem >> 4, f4 = rem & 15;
                const float4* src = B4 + ((size_t)(kt0 + kt) * NT + n0t + ntile) * 16 + f4;
                cpa16(smBase + (uint32_t)((3 + st) * 512 + idx) * 16, src);
            }
        }
        cpa_commit();
    };

    float acc[4][4][4];
    #pragma unroll
    for (int mi = 0; mi < 4; mi++)
        #pragma unroll
        for (int ni = 0; ni < 4; ni++)
            #pragma unroll
            for (int q = 0; q < 4; q++) acc[mi][ni][q] = 0.f;

    const int NIT = K / 16;
    prefetch(0, 0);
    if (1 < NIT) prefetch(1, 1);

    const int fl = t * 8 + g;   // fragment lane index

    for (int it = 0; it < NIT; it++) {
        const int st = it % 3;
        if (it + 2 < NIT) {
            prefetch(it + 2, (it + 2) % 3);
            cpa_wait2();
        } else if (it + 1 < NIT) {
            cpa_wait1();
        } else {
            cpa_wait0();
        }
        __syncthreads();

        const float4* Ab4 = smg4 + st * 512;
        const float2* Bb2 = (const float2*)(smg4 + (3 + st) * 512);
        #pragma unroll
        for (int kt = 0; kt < 2; kt++) {
            float4 af4[4];
            float2 bf2[4];
            #pragma unroll
            for (int mi = 0; mi < 4; mi++)
                af4[mi] = Ab4[kt * 256 + (wmt + mi) * 32 + fl];
            #pragma unroll
            for (int ni = 0; ni < 4; ni++)
                bf2[ni] = Bb2[kt * 512 + ((wn >> 3) + ni) * 32 + fl];
            #pragma unroll
            for (int mi = 0; mi < 4; mi++) {
                uint32_t a[4] = { __float_as_uint(af4[mi].x), __float_as_uint(af4[mi].y),
                                  __float_as_uint(af4[mi].z), __float_as_uint(af4[mi].w) };
                #pragma unroll
                for (int ni = 0; ni < 4; ni++) {
                    uint32_t b[2] = { __float_as_uint(bf2[ni].x), __float_as_uint(bf2[ni].y) };
                    mma_tf32(acc[mi][ni], a, b);
                }
            }
        }
        __syncthreads();
    }

    // epilogue
    #pragma unroll
    for (int mi = 0; mi < 4; mi++) {
        const int r0 = m0t * 16 + (warp >> 2) * 64 + mi * 16 + g;
        #pragma unroll
        for (int ni = 0; ni < 4; ni++) {
            const int c0 = n0 + wn + ni * 8 + 2 * t;
            const float bb0 = bias[c0], bb1 = bias[c0 + 1];
            float v0 = acc[mi][ni][0] + bb0;
            float v1 = acc[mi][ni][1] + bb1;
            float v2 = acc[mi][ni][2] + bb0;
            float v3 = acc[mi][ni][3] + bb1;
            if (GELU) {
                v0 = gelu_exact(v0); v1 = gelu_exact(v1);
                v2 = gelu_exact(v2); v3 = gelu_exact(v3);
            }
            if (ROUND_OUT) {
                v0 = tf32r(v0); v1 = tf32r(v1);
                v2 = tf32r(v2); v3 = tf32r(v3);
            }
            if (PERM_OUT) {
                C[aperm(r0,     c0,     MT_G)] = v0;
                C[aperm(r0,     c0 + 1, MT_G)] = v1;
                C[aperm(r0 + 8, c0,     MT_G)] = v2;
                C[aperm(r0 + 8, c0 + 1, MT_G)] = v3;
            } else {
                *(float2*)(C + (size_t)r0 * ldc + c0)       = make_float2(v0, v1);
                *(float2*)(C + (size_t)(r0 + 8) * ldc + c0) = make_float2(v2, v3);
            }
        }
    }
}

// ---------------- final assembly: concat + posenc + time embedding ----------------
__global__ void assemble_kernel(const float* __restrict__ emb,
                                const float* __restrict__ coords,
                                const float* __restrict__ vis,
                                const float* __restrict__ conf,
                                float* __restrict__ out)
{
    const int n = blockIdx.x, s = blockIdx.y;
    const int sn = s * N_ + n;

    float rfx = 0.f, rfy = 0.f, rbx = 0.f, rby = 0.f;
    const float cx = coords[sn * 2], cy = coords[sn * 2 + 1];
    if (s < S_ - 1) {
        rfx = cx - coords[((s + 1) * N_ + n) * 2];
        rfy = cy - coords[((s + 1) * N_ + n) * 2 + 1];
    }
    if (s > 0) {
        rbx = cx - coords[((s - 1) * N_ + n) * 2];
        rby = cy - coords[((s - 1) * N_ + n) * 2 + 1];
    }
    float p4[4];
    p4[0] = rfx / 64.f;
    p4[1] = rfy / 48.f;
    p4[2] = rbx / 64.f;
    p4[3] = rby / 48.f;

    float* orow = out + (size_t)(n * S_ + s) * 854;
    for (int f = threadIdx.x; f < 854; f += 256) {
        float v;
        if (f == 0)      v = vis[sn];
        else if (f == 1) v = conf[sn];
        else if (f < 770) {
            const int lev = (f - 2) >> 8;
            const int c   = (f - 2) & 255;
            v = emb[((size_t)(lev * 4096 + sn)) * 256 + c];
        } else {
            const int j = f - 770;
            if (j < 4) v = p4[j];
            else if (j < 44) {
                const int i = (j - 4) >> 2, q = (j - 4) & 3;
                v = sinf(exp2f((float)i) * p4[q]);
            } else {
                const int i = (j - 44) >> 2, q = (j - 44) & 3;
                v = sinf(exp2f((float)i) * p4[q] + 1.5707963267948966f);
            }
        }
        const int i2 = (f < 427) ? f : f - 427;
        const float omega = expf(-9.210340371976184f * (float)i2 / 427.0f);
        const float ang = (float)s * omega;
        v += (f < 427) ? sinf(ang) : cosf(ang);
        orow[f] = v;
    }
}

// ---------------- launch ----------------
extern "C" void kernel_launch(void* const* d_in, const int* in_sizes, int n_in,
                              void* d_out, int out_size)
{
    (void)in_sizes; (void)n_in; (void)out_size;
    const float* fm0    = (const float*)d_in[0];
    const float* fm1    = (const float*)d_in[1];
    const float* fm2    = (const float*)d_in[2];
    const float* coords = (const float*)d_in[3];
    const float* tf0    = (const float*)d_in[4];
    const float* tf1    = (const float*)d_in[5];
    const float* tf2    = (const float*)d_in[6];
    const float* vis    = (const float*)d_in[7];
    const float* conf   = (const float*)d_in[8];
    const float* W1     = (const float*)d_in[9];
    const float* b1     = (const float*)d_in[10];
    const float* W2     = (const float*)d_in[11];
    const float* W2b    = (const float*)d_in[12];
    float* out = (float*)d_out;

    float *fT, *vol, *hbuf, *ebuf, *w1r, *w2r;
    cudaGetSymbolAddress((void**)&fT,   g_fmapT);
    cudaGetSymbolAddress((void**)&vol,  g_vol);
    cudaGetSymbolAddress((void**)&hbuf, g_h);
    cudaGetSymbolAddress((void**)&ebuf, g_emb);
    cudaGetSymbolAddress((void**)&w1r,  g_w1r);
    cudaGetSymbolAddress((void**)&w2r,  g_w2r);

    cudaFuncSetAttribute(vol_kernel, cudaFuncAttributeMaxDynamicSharedMemorySize, VOL_SMEM);
    cudaFuncSetAttribute(tf32_gemm_perm<true,  true,  true >, cudaFuncAttributeMaxDynamicSharedMemorySize, GEMM_SMEM);
    cudaFuncSetAttribute(tf32_gemm_perm<false, false, false>, cudaFuncAttributeMaxDynamicSharedMemorySize, GEMM_SMEM);

    transpose_all_kernel<<<dim3(126, 4, 16), dim3(32, 8)>>>(fm0, fm1, fm2, fT);

    const int NP = KPAD * 384 + 384 * 256;
    pack_weights_kernel<<<(NP + 255) / 256, 256>>>(W1, w1r, W2, w2r);

    vol_kernel<<<dim3(N_, S_, 3), 256, VOL_SMEM>>>(fT, tf0, tf1, tf2, coords, vol);

    tf32_gemm_perm<true,  true,  true ><<<dim3(3, 96), 256, GEMM_SMEM>>>(
        (const float4*)vol,  MT_G, (const float4*)w1r, 48, b1,  hbuf, 0,   KPAD);
    tf32_gemm_perm<false, false, false><<<dim3(2, 96), 256, GEMM_SMEM>>>(
        (const float4*)hbuf, MT_G, (const float4*)w2r, 32, W2b, ebuf, 256, 384);

    assemble_kernel<<<dim3(N_, S_), 256>>>(ebuf, coords, vis, conf, out);
}

// round 13
// speedup vs baseline: 1.3274x; 1.3274x over previous
#include <cuda_runtime.h>
#include <cuda_bf16.h>
#include <math.h>
#include <stdint.h>

// ---------------- constants ----------------
#define S_   16
#define N_   256
#define D_   128
#define RR   49
#define K1   2401            // 49*49
#define VSTR 2416            // padded vol row stride (mult of 16)
#define ROWS_T 12288         // 3 levels * 16 * 256

// fmapT offsets
#define FT1_OFF 6291456      // 16*48*64*128
#define FT2_OFF 7864320      // + 16*24*32*128

// ---------------- scratch (static device memory; no allocs) ----------------
__device__ float g_fmapT[8257536];           // all 3 transposed fmaps
__device__ float g_vol[ROWS_T * VSTR];       // 12288 x 2416
__device__ float g_h[ROWS_T * 384];
__device__ float g_emb[ROWS_T * 256];
__device__ float g_w1r[K1 * 384];            // tf32-rounded W1
__device__ float g_w2r[384 * 256];           // tf32-rounded W2

// ---------------- helpers ----------------
__device__ __forceinline__ uint32_t f2tf32(float f)
{
    uint32_t r;
    asm("cvt.rna.tf32.f32 %0, %1;" : "=r"(r) : "f"(f));
    return r;
}

__device__ __forceinline__ float tf32r(float f) { return __uint_as_float(f2tf32(f)); }

__device__ __forceinline__ void mma_tf32(float* c, const uint32_t* a, const uint32_t* b)
{
    asm volatile(
        "mma.sync.aligned.m16n8k8.row.col.f32.tf32.tf32.f32 "
        "{%0,%1,%2,%3}, {%4,%5,%6,%7}, {%8,%9}, {%0,%1,%2,%3};"
        : "+f"(c[0]), "+f"(c[1]), "+f"(c[2]), "+f"(c[3])
        : "r"(a[0]), "r"(a[1]), "r"(a[2]), "r"(a[3]), "r"(b[0]), "r"(b[1]));
}

__device__ __forceinline__ void cpa16(uint32_t dst, const void* src, bool pred)
{
    asm volatile("cp.async.ca.shared.global [%0], [%1], 16, %2;"
                 :: "r"(dst), "l"(src), "r"(pred ? 16 : 0) : "memory");
}
__device__ __forceinline__ void cpa_commit() { asm volatile("cp.async.commit_group;" ::: "memory"); }
__device__ __forceinline__ void cpa_wait0()  { asm volatile("cp.async.wait_group 0;" ::: "memory"); }
__device__ __forceinline__ void cpa_wait1()  { asm volatile("cp.async.wait_group 1;" ::: "memory"); }
__device__ __forceinline__ void cpa_wait2()  { asm volatile("cp.async.wait_group 2;" ::: "memory"); }

// ---------------- fused transpose [S,D,H,W] -> [S,H*W,D], all 3 levels -------
__global__ void transpose_all_kernel(const float* __restrict__ fm0,
                                     const float* __restrict__ fm1,
                                     const float* __restrict__ fm2,
                                     float* __restrict__ dstBase)
{
    __shared__ float tile[32][33];
    int bx = blockIdx.x;
    const float* src;
    float* dst;
    int HW;
    if (bx < 96)       { src = fm0; dst = dstBase;           HW = 3072; }
    else if (bx < 120) { src = fm1; dst = dstBase + FT1_OFF; HW = 768;  bx -= 96; }
    else               { src = fm2; dst = dstBase + FT2_OFF; HW = 192;  bx -= 120; }

    int s   = blockIdx.z;
    int hw0 = bx * 32;
    int d0  = blockIdx.y * 32;
    int tx  = threadIdx.x;
    for (int i = threadIdx.y; i < 32; i += 8)
        tile[i][tx] = src[(size_t)(s * D_ + d0 + i) * HW + hw0 + tx];
    __syncthreads();
    for (int i = threadIdx.y; i < 32; i += 8)
        dst[(size_t)(s * HW + hw0 + i) * D_ + d0 + tx] = tile[tx][i];
}

// ---------------- round both weight tensors to tf32-representable fp32 -------
__global__ void round2_kernel(const float* __restrict__ W1s, float* __restrict__ w1d, int n1,
                              const float* __restrict__ W2s, float* __restrict__ w2d, int n2)
{
    int i = blockIdx.x * 256 + threadIdx.x;
    if (i < n1) w1d[i] = tf32r(W1s[i]);
    else {
        int j = i - n1;
        if (j < n2) w2d[j] = tf32r(W2s[j]);
    }
}

// ---------------- vol kernel: per-(s,n,lev) block, 8x8 patch -> mma -> bilinear
#define VAW 132
#define VA_SZ (64 * VAW)    // 8448 floats
#define VB_SZ (56 * VAW)    // 7392 floats
#define VOL_SMEM ((VA_SZ + VB_SZ) * 4)   // 63360 B

__global__ __launch_bounds__(256)
void vol_kernel(const float* __restrict__ fmTbase,
                const float* __restrict__ tf0,
                const float* __restrict__ tf1,
                const float* __restrict__ tf2,
                const float* __restrict__ coords, float* __restrict__ vol)
{
    extern __shared__ float smv[];
    float* As = smv;            // [64][132]
    float* Bs = smv + VA_SZ;    // [56][132]

    const int n = blockIdx.x, s = blockIdx.y, lev = blockIdx.z;
    const int tid = threadIdx.x, lane = tid & 31, wp = tid >> 5;

    int H, W, off;
    float invscale;
    const float* tfs;
    if (lev == 0)      { H = 48; W = 64; off = 0;       invscale = 1.0f;  tfs = tf0; }
    else if (lev == 1) { H = 24; W = 32; off = FT1_OFF; invscale = 0.5f;  tfs = tf1; }
    else               { H = 12; W = 16; off = FT2_OFF; invscale = 0.25f; tfs = tf2; }

    const int sn = s * N_ + n;
    const float cx = coords[sn * 2 + 0] * invscale;
    const float cy = coords[sn * 2 + 1] * invscale;
    const float fxx = floorf(cx), fyy = floorf(cy);
    const int   ix0 = (int)fxx,   iy0 = (int)fyy;
    const float fx = cx - fxx,    fy = cy - fyy;
    const float w00 = (1.f - fx) * (1.f - fy);
    const float w01 = fx * (1.f - fy);
    const float w10 = (1.f - fx) * fy;
    const float w11 = fx * fy;
    const float* base = fmTbase + off + (size_t)s * H * W * D_;

    // gather raw 8x8 texel patch: warp per texel row m; lane owns 4 channels
    #pragma unroll
    for (int m = wp; m < 64; m += 8) {
        const int ty = m >> 3, tx = m & 7;
        const int yy = iy0 + ty - 3, xx = ix0 + tx - 3;
        float4 t = make_float4(0.f, 0.f, 0.f, 0.f);
        if ((yy >= 0) && (yy < H) && (xx >= 0) && (xx < W))
            t = *(const float4*)(base + ((long)yy * W + xx) * D_ + 4 * lane);
        *(float4*)&As[m * VAW + 4 * lane] =
            make_float4(tf32r(t.x), tf32r(t.y), tf32r(t.z), tf32r(t.w));
    }
    // gather tf: warp per ij; lane owns 4 channels
    for (int ij = wp; ij < RR; ij += 8) {
        float4 t = *(const float4*)(tfs + ((long)ij * N_ + n) * D_ + 4 * lane);
        *(float4*)&Bs[ij * VAW + 4 * lane] =
            make_float4(tf32r(t.x), tf32r(t.y), tf32r(t.z), tf32r(t.w));
    }
    __syncthreads();

    float* vrow = vol + (size_t)(lev * 4096 + sn) * VSTR;
    if (tid < VSTR - K1) vrow[K1 + tid] = 0.f;

    // mma: warp -> m tile (warp&3)*16, n half (warp>>2); C = texels . tf
    const int wm  = (wp & 3) * 16;
    const int nh  = wp >> 2;
    const int nt0 = nh ? 4 : 0;
    const int ntN = nh ? 3 : 4;
    const int t = lane & 3, g = lane >> 2;
    const uint32_t* Au = (const uint32_t*)As;
    const uint32_t* Bu = (const uint32_t*)Bs;

    float acc[4][4];
    #pragma unroll
    for (int i = 0; i < 4; i++)
        #pragma unroll
        for (int q = 0; q < 4; q++) acc[i][q] = 0.f;

    #pragma unroll
    for (int kb = 0; kb < 16; kb++) {
        const int kc = kb * 8 + t;
        uint32_t a[4];
        const int ra = (wm + g) * VAW + kc;
        const int rb = (wm + g + 8) * VAW + kc;
        a[0] = Au[ra];     a[1] = Au[rb];
        a[2] = Au[ra + 4]; a[3] = Au[rb + 4];
        #pragma unroll
        for (int ni = 0; ni < 4; ni++) {
            if (ni >= ntN) break;
            const int nb = ((nt0 + ni) * 8 + g) * VAW + kc;
            uint32_t b[2];
            b[0] = Bu[nb]; b[1] = Bu[nb + 4];
            mma_tf32(acc[ni], a, b);
        }
    }

    // store C to smem (reuse region), then bilinear-combine in output space
    __syncthreads();
    float* Cs = smv;    // [64][56]
    #pragma unroll
    for (int ni = 0; ni < 4; ni++) {
        if (ni >= ntN) break;
        const int col0 = (nt0 + ni) * 8 + 2 * t;
        *(float2*)&Cs[(wm + g) * 56 + col0]     = make_float2(acc[ni][0], acc[ni][1]);
        *(float2*)&Cs[(wm + g + 8) * 56 + col0] = make_float2(acc[ni][2], acc[ni][3]);
    }
    __syncthreads();

    for (int idx = tid; idx < K1; idx += 256) {
        const int hw = idx / 49, ij = idx - hw * 49;
        const int h = hw / 7,  w = hw - h * 7;
        const int m00 = h * 8 + w;
        const float v = w00 * Cs[m00 * 56 + ij]
                      + w01 * Cs[(m00 + 1) * 56 + ij]
                      + w10 * Cs[(m00 + 8) * 56 + ij]
                      + w11 * Cs[(m00 + 9) * 56 + ij];
        vrow[idx] = tf32r(v);
    }
}

// ---------------- 3-stage tf32 GEMM, 128x128 tile, 4 warps of 64x64 ---------
__device__ __forceinline__ float gelu_exact(float v)
{
    return 0.5f * v * (1.f + erff(v * 0.7071067811865475f));
}

#define AST 20   // A smem word stride per m row (16 k + pad)
#define BST 136  // B smem word stride per k row (128 n + pad)
#define STG_A (128 * AST)   // 2560 words
#define STG_B (16 * BST)    // 2176 words
#define GEMM_SMEM (3 * (STG_A + STG_B) * 4)   // 56832 B

template <bool GELU, bool ROUND_OUT>
__global__ __launch_bounds__(128, 2)
void tf32_gemm_pipe(const float* __restrict__ A, int lda,
                    const float* __restrict__ B, int ldb,
                    const float* __restrict__ bias,
                    float* __restrict__ C, int ldc,
                    int K, int Kvalid)
{
    extern __shared__ float smg[];
    float* AsBase = smg;                    // 3 x STG_A
    float* BsBase = smg + 3 * STG_A;        // 3 x STG_B

    const int tid  = threadIdx.x;
    const int lane = tid & 31;
    const int warp = tid >> 5;              // 0..3
    const int m0 = blockIdx.y * 128, n0 = blockIdx.x * 128;
    const int wm = (warp >> 1) * 64, wn = (warp & 1) * 64;
    const int t = lane & 3, g = lane >> 2;

    // staging assignments (128 threads):
    // A: 128 rows x 4 k-quads -> thread = row, 4 cpa16 each
    // B: 16 k-rows x 32 col-quads -> thread covers rows (tid>>5)+4q, col (tid&31)*4
    const int am  = tid;
    const int bk0 = tid >> 5;               // 0..3
    const int bnc = (tid & 31) * 4;

    uint32_t sA[3], sB[3];
    {
        uint32_t a = (uint32_t)__cvta_generic_to_shared(AsBase);
        uint32_t b = (uint32_t)__cvta_generic_to_shared(BsBase);
        #pragma unroll
        for (int st = 0; st < 3; st++) {
            sA[st] = a + (st * STG_A + am * AST) * 4;
            sB[st] = b + (st * STG_B + bk0 * BST + bnc) * 4;
        }
    }
    const float* gA = A + (size_t)(m0 + am) * lda;
    const float* gB = B + (size_t)bk0 * ldb + n0 + bnc;

    const int NIT = K / 16;

    auto prefetch = [&](int it, int st) {
        const int k0 = it * 16;
        #pragma unroll
        for (int q = 0; q < 4; q++)
            cpa16(sA[st] + q * 16, gA + k0 + q * 4, true);
        #pragma unroll
        for (int q = 0; q < 4; q++)
            cpa16(sB[st] + q * 4 * BST * 4,
                  gB + (size_t)(k0 + q * 4) * ldb,
                  k0 + bk0 + q * 4 < Kvalid);
        cpa_commit();
    };

    float acc[4][8][4];
    #pragma unroll
    for (int mi = 0; mi < 4; mi++)
        #pragma unroll
        for (int ni = 0; ni < 8; ni++)
            #pragma unroll
            for (int q = 0; q < 4; q++) acc[mi][ni][q] = 0.f;

    prefetch(0, 0);
    if (1 < NIT) prefetch(1, 1);

    for (int it = 0; it < NIT; it++) {
        const int st = it % 3;
        if (it + 2 < NIT) {
            prefetch(it + 2, (it + 2) % 3);
            cpa_wait2();
        } else if (it + 1 < NIT) {
            cpa_wait1();
        } else {
            cpa_wait0();
        }
        __syncthreads();

        const float* Ab = AsBase + st * STG_A;
        const float* Bb = BsBase + st * STG_B;
        #pragma unroll
        for (int kb = 0; kb < 16; kb += 8) {
            uint32_t af[4][4], bf[8][2];
            #pragma unroll
            for (int mi = 0; mi < 4; mi++) {
                const int r = (wm + mi * 16 + g) * AST + kb + t;
                af[mi][0] = __float_as_uint(Ab[r]);
                af[mi][1] = __float_as_uint(Ab[r + 8 * AST]);
                af[mi][2] = __float_as_uint(Ab[r + 4]);
                af[mi][3] = __float_as_uint(Ab[r + 8 * AST + 4]);
            }
            #pragma unroll
            for (int ni = 0; ni < 8; ni++) {
                const int cidx = (kb + t) * BST + wn + ni * 8 + g;
                bf[ni][0] = __float_as_uint(Bb[cidx]);
                bf[ni][1] = __float_as_uint(Bb[cidx + 4 * BST]);
            }
            #pragma unroll
            for (int mi = 0; mi < 4; mi++)
                #pragma unroll
                for (int ni = 0; ni < 8; ni++)
                    mma_tf32(acc[mi][ni], af[mi], bf[ni]);
        }
        __syncthreads();
    }

    // epilogue: bias (+gelu) (+tf32 round), write C
    #pragma unroll
    for (int mi = 0; mi < 4; mi++) {
        const int r0 = m0 + wm + mi * 16 + g;
        #pragma unroll
        for (int ni = 0; ni < 8; ni++) {
            const int c0 = n0 + wn + ni * 8 + 2 * t;
            const float bb0 = bias[c0], bb1 = bias[c0 + 1];
            float v0 = acc[mi][ni][0] + bb0;
            float v1 = acc[mi][ni][1] + bb1;
            float v2 = acc[mi][ni][2] + bb0;
            float v3 = acc[mi][ni][3] + bb1;
            if (GELU) {
                v0 = gelu_exact(v0); v1 = gelu_exact(v1);
                v2 = gelu_exact(v2); v3 = gelu_exact(v3);
            }
            if (ROUND_OUT) {
                v0 = tf32r(v0); v1 = tf32r(v1);
                v2 = tf32r(v2); v3 = tf32r(v3);
            }
            *(float2*)(C + (size_t)r0 * ldc + c0)       = make_float2(v0, v1);
            *(float2*)(C + (size_t)(r0 + 8) * ldc + c0) = make_float2(v2, v3);
        }
    }
}

// ---------------- final assembly: concat + posenc + time embedding ----------------
__global__ void assemble_kernel(const float* __restrict__ emb,
                                const float* __restrict__ coords,
                                const float* __restrict__ vis,
                                const float* __restrict__ conf,
                                float* __restrict__ out)
{
    const int n = blockIdx.x, s = blockIdx.y;
    const int sn = s * N_ + n;

    float rfx = 0.f, rfy = 0.f, rbx = 0.f, rby = 0.f;
    const float cx = coords[sn * 2], cy = coords[sn * 2 + 1];
    if (s < S_ - 1) {
        rfx = cx - coords[((s + 1) * N_ + n) * 2];
        rfy = cy - coords[((s + 1) * N_ + n) * 2 + 1];
    }
    if (s > 0) {
        rbx = cx - coords[((s - 1) * N_ + n) * 2];
        rby = cy - coords[((s - 1) * N_ + n) * 2 + 1];
    }
    float p4[4];
    p4[0] = rfx / 64.f;
    p4[1] = rfy / 48.f;
    p4[2] = rbx / 64.f;
    p4[3] = rby / 48.f;

    float* orow = out + (size_t)(n * S_ + s) * 854;
    for (int f = threadIdx.x; f < 854; f += 256) {
        float v;
        if (f == 0)      v = vis[sn];
        else if (f == 1) v = conf[sn];
        else if (f < 770) {
            const int lev = (f - 2) >> 8;
            const int c   = (f - 2) & 255;
            v = emb[((size_t)(lev * 4096 + sn)) * 256 + c];
        } else {
            const int j = f - 770;
            if (j < 4) v = p4[j];
            else if (j < 44) {
                const int i = (j - 4) >> 2, q = (j - 4) & 3;
                v = sinf(exp2f((float)i) * p4[q]);
            } else {
                const int i = (j - 44) >> 2, q = (j - 44) & 3;
                v = sinf(exp2f((float)i) * p4[q] + 1.5707963267948966f);
            }
        }
        const int i2 = (f < 427) ? f : f - 427;
        const float omega = expf(-9.210340371976184f * (float)i2 / 427.0f);
        const float ang = (float)s * omega;
        v += (f < 427) ? sinf(ang) : cosf(ang);
        orow[f] = v;
    }
}

// ---------------- launch ----------------
extern "C" void kernel_launch(void* const* d_in, const int* in_sizes, int n_in,
                              void* d_out, int out_size)
{
    (void)in_sizes; (void)n_in; (void)out_size;
    const float* fm0    = (const float*)d_in[0];
    const float* fm1    = (const float*)d_in[1];
    const float* fm2    = (const float*)d_in[2];
    const float* coords = (const float*)d_in[3];
    const float* tf0    = (const float*)d_in[4];
    const float* tf1    = (const float*)d_in[5];
    const float* tf2    = (const float*)d_in[6];
    const float* vis    = (const float*)d_in[7];
    const float* conf   = (const float*)d_in[8];
    const float* W1     = (const float*)d_in[9];
    const float* b1     = (const float*)d_in[10];
    const float* W2     = (const float*)d_in[11];
    const float* W2b    = (const float*)d_in[12];
    float* out = (float*)d_out;

    float *fT, *vol, *hbuf, *ebuf, *w1r, *w2r;
    cudaGetSymbolAddress((void**)&fT,   g_fmapT);
    cudaGetSymbolAddress((void**)&vol,  g_vol);
    cudaGetSymbolAddress((void**)&hbuf, g_h);
    cudaGetSymbolAddress((void**)&ebuf, g_emb);
    cudaGetSymbolAddress((void**)&w1r,  g_w1r);
    cudaGetSymbolAddress((void**)&w2r,  g_w2r);

    cudaFuncSetAttribute(vol_kernel, cudaFuncAttributeMaxDynamicSharedMemorySize, VOL_SMEM);
    cudaFuncSetAttribute(tf32_gemm_pipe<true,  true >, cudaFuncAttributeMaxDynamicSharedMemorySize, GEMM_SMEM);
    cudaFuncSetAttribute(tf32_gemm_pipe<false, false>, cudaFuncAttributeMaxDynamicSharedMemorySize, GEMM_SMEM);

    // launch order puts gemm1 at profiled slot #4
    transpose_all_kernel<<<dim3(126, 4, 16), dim3(32, 8)>>>(fm0, fm1, fm2, fT);

    const int NR = K1 * 384 + 384 * 256;
    round2_kernel<<<(NR + 255) / 256, 256>>>(W1, w1r, K1 * 384, W2, w2r, 384 * 256);

    vol_kernel<<<dim3(N_, S_, 3), 256, VOL_SMEM>>>(fT, tf0, tf1, tf2, coords, vol);

    tf32_gemm_pipe<true,  true ><<<dim3(3, 96), 128, GEMM_SMEM>>>(vol,  VSTR, w1r, 384, b1,  hbuf, 384, VSTR, K1);
    tf32_gemm_pipe<false, false><<<dim3(2, 96), 128, GEMM_SMEM>>>(hbuf, 384,  w2r, 256, W2b, ebuf, 256, 384,  384);

    assemble_kernel<<<dim3(N_, S_), 256>>>(ebuf, coords, vis, conf, out);
}

// round 14
// speedup vs baseline: 1.3399x; 1.0095x over previous
#include <cuda_runtime.h>
#include <cuda_bf16.h>
#include <math.h>
#include <stdint.h>

// ---------------- constants ----------------
#define S_   16
#define N_   256
#define D_   128
#define RR   49
#define K1   2401            // 49*49
#define VSTR 2416            // padded vol row stride (mult of 16)
#define ROWS_T 12288         // 3 levels * 16 * 256

// fmapT offsets
#define FT1_OFF 6291456      // 16*48*64*128
#define FT2_OFF 7864320      // + 16*24*32*128

// ---------------- scratch (static device memory; no allocs) ----------------
__device__ float g_fmapT[8257536];           // all 3 transposed fmaps
__device__ float g_vol[ROWS_T * VSTR];       // 12288 x 2416
__device__ float g_h[ROWS_T * 384];
__device__ float g_emb[ROWS_T * 256];
__device__ float g_w1r[K1 * 384];            // tf32-rounded W1
__device__ float g_w2r[384 * 256];           // tf32-rounded W2

// ---------------- helpers ----------------
__device__ __forceinline__ uint32_t f2tf32(float f)
{
    uint32_t r;
    asm("cvt.rna.tf32.f32 %0, %1;" : "=r"(r) : "f"(f));
    return r;
}

__device__ __forceinline__ float tf32r(float f) { return __uint_as_float(f2tf32(f)); }

__device__ __forceinline__ void mma_tf32(float* c, const uint32_t* a, const uint32_t* b)
{
    asm volatile(
        "mma.sync.aligned.m16n8k8.row.col.f32.tf32.tf32.f32 "
        "{%0,%1,%2,%3}, {%4,%5,%6,%7}, {%8,%9}, {%0,%1,%2,%3};"
        : "+f"(c[0]), "+f"(c[1]), "+f"(c[2]), "+f"(c[3])
        : "r"(a[0]), "r"(a[1]), "r"(a[2]), "r"(a[3]), "r"(b[0]), "r"(b[1]));
}

__device__ __forceinline__ void cpa16(uint32_t dst, const void* src, bool pred)
{
    asm volatile("cp.async.ca.shared.global [%0], [%1], 16, %2;"
                 :: "r"(dst), "l"(src), "r"(pred ? 16 : 0) : "memory");
}
__device__ __forceinline__ void cpa_commit() { asm volatile("cp.async.commit_group;" ::: "memory"); }
__device__ __forceinline__ void cpa_wait0()  { asm volatile("cp.async.wait_group 0;" ::: "memory"); }
__device__ __forceinline__ void cpa_wait1()  { asm volatile("cp.async.wait_group 1;" ::: "memory"); }

// ---------------- fused transpose [S,D,H,W] -> [S,H*W,D], all 3 levels -------
__global__ void transpose_all_kernel(const float* __restrict__ fm0,
                                     const float* __restrict__ fm1,
                                     const float* __restrict__ fm2,
                                     float* __restrict__ dstBase)
{
    __shared__ float tile[32][33];
    int bx = blockIdx.x;
    const float* src;
    float* dst;
    int HW;
    if (bx < 96)       { src = fm0; dst = dstBase;           HW = 3072; }
    else if (bx < 120) { src = fm1; dst = dstBase + FT1_OFF; HW = 768;  bx -= 96; }
    else               { src = fm2; dst = dstBase + FT2_OFF; HW = 192;  bx -= 120; }

    int s   = blockIdx.z;
    int hw0 = bx * 32;
    int d0  = blockIdx.y * 32;
    int tx  = threadIdx.x;
    for (int i = threadIdx.y; i < 32; i += 8)
        tile[i][tx] = src[(size_t)(s * D_ + d0 + i) * HW + hw0 + tx];
    __syncthreads();
    for (int i = threadIdx.y; i < 32; i += 8)
        dst[(size_t)(s * HW + hw0 + i) * D_ + d0 + tx] = tile[tx][i];
}

// ---------------- round both weight tensors to tf32-representable fp32 -------
__global__ void round2_kernel(const float* __restrict__ W1s, float* __restrict__ w1d, int n1,
                              const float* __restrict__ W2s, float* __restrict__ w2d, int n2)
{
    int i = blockIdx.x * 256 + threadIdx.x;
    if (i < n1) w1d[i] = tf32r(W1s[i]);
    else {
        int j = i - n1;
        if (j < n2) w2d[j] = tf32r(W2s[j]);
    }
}

// ---------------- vol kernel: per-(s,n,lev) block, 8x8 patch -> mma -> bilinear
#define VAW 132
#define VA_SZ (64 * VAW)    // 8448 floats
#define VB_SZ (56 * VAW)    // 7392 floats
#define VOL_SMEM ((VA_SZ + VB_SZ) * 4)   // 63360 B

__global__ __launch_bounds__(256)
void vol_kernel(const float* __restrict__ fmTbase,
                const float* __restrict__ tf0,
                const float* __restrict__ tf1,
                const float* __restrict__ tf2,
                const float* __restrict__ coords, float* __restrict__ vol)
{
    extern __shared__ float smv[];
    float* As = smv;            // [64][132]
    float* Bs = smv + VA_SZ;    // [56][132]

    const int n = blockIdx.x, s = blockIdx.y, lev = blockIdx.z;
    const int tid = threadIdx.x, lane = tid & 31, wp = tid >> 5;

    int H, W, off;
    float invscale;
    const float* tfs;
    if (lev == 0)      { H = 48; W = 64; off = 0;       invscale = 1.0f;  tfs = tf0; }
    else if (lev == 1) { H = 24; W = 32; off = FT1_OFF; invscale = 0.5f;  tfs = tf1; }
    else               { H = 12; W = 16; off = FT2_OFF; invscale = 0.25f; tfs = tf2; }

    const int sn = s * N_ + n;
    const float cx = coords[sn * 2 + 0] * invscale;
    const float cy = coords[sn * 2 + 1] * invscale;
    const float fxx = floorf(cx), fyy = floorf(cy);
    const int   ix0 = (int)fxx,   iy0 = (int)fyy;
    const float fx = cx - fxx,    fy = cy - fyy;
    const float w00 = (1.f - fx) * (1.f - fy);
    const float w01 = fx * (1.f - fy);
    const float w10 = (1.f - fx) * fy;
    const float w11 = fx * fy;
    const float* base = fmTbase + off + (size_t)s * H * W * D_;

    // gather raw 8x8 texel patch: warp per texel row m; lane owns 4 channels
    #pragma unroll
    for (int m = wp; m < 64; m += 8) {
        const int ty = m >> 3, tx = m & 7;
        const int yy = iy0 + ty - 3, xx = ix0 + tx - 3;
        float4 t = make_float4(0.f, 0.f, 0.f, 0.f);
        if ((yy >= 0) && (yy < H) && (xx >= 0) && (xx < W))
            t = *(const float4*)(base + ((long)yy * W + xx) * D_ + 4 * lane);
        *(float4*)&As[m * VAW + 4 * lane] =
            make_float4(tf32r(t.x), tf32r(t.y), tf32r(t.z), tf32r(t.w));
    }
    // gather tf: warp per ij; lane owns 4 channels
    for (int ij = wp; ij < RR; ij += 8) {
        float4 t = *(const float4*)(tfs + ((long)ij * N_ + n) * D_ + 4 * lane);
        *(float4*)&Bs[ij * VAW + 4 * lane] =
            make_float4(tf32r(t.x), tf32r(t.y), tf32r(t.z), tf32r(t.w));
    }
    __syncthreads();

    float* vrow = vol + (size_t)(lev * 4096 + sn) * VSTR;
    if (tid < VSTR - K1) vrow[K1 + tid] = 0.f;

    // mma: warp -> m tile (warp&3)*16, n half (warp>>2); C = texels . tf
    const int wm  = (wp & 3) * 16;
    const int nh  = wp >> 2;
    const int nt0 = nh ? 4 : 0;
    const int ntN = nh ? 3 : 4;
    const int t = lane & 3, g = lane >> 2;
    const uint32_t* Au = (const uint32_t*)As;
    const uint32_t* Bu = (const uint32_t*)Bs;

    float acc[4][4];
    #pragma unroll
    for (int i = 0; i < 4; i++)
        #pragma unroll
        for (int q = 0; q < 4; q++) acc[i][q] = 0.f;

    #pragma unroll
    for (int kb = 0; kb < 16; kb++) {
        const int kc = kb * 8 + t;
        uint32_t a[4];
        const int ra = (wm + g) * VAW + kc;
        const int rb = (wm + g + 8) * VAW + kc;
        a[0] = Au[ra];     a[1] = Au[rb];
        a[2] = Au[ra + 4]; a[3] = Au[rb + 4];
        #pragma unroll
        for (int ni = 0; ni < 4; ni++) {
            if (ni >= ntN) break;
            const int nb = ((nt0 + ni) * 8 + g) * VAW + kc;
            uint32_t b[2];
            b[0] = Bu[nb]; b[1] = Bu[nb + 4];
            mma_tf32(acc[ni], a, b);
        }
    }

    // store C to smem (reuse region), then bilinear-combine in output space
    __syncthreads();
    float* Cs = smv;    // [64][56]
    #pragma unroll
    for (int ni = 0; ni < 4; ni++) {
        if (ni >= ntN) break;
        const int col0 = (nt0 + ni) * 8 + 2 * t;
        *(float2*)&Cs[(wm + g) * 56 + col0]     = make_float2(acc[ni][0], acc[ni][1]);
        *(float2*)&Cs[(wm + g + 8) * 56 + col0] = make_float2(acc[ni][2], acc[ni][3]);
    }
    __syncthreads();

    for (int idx = tid; idx < K1; idx += 256) {
        const int hw = idx / 49, ij = idx - hw * 49;
        const int h = hw / 7,  w = hw - h * 7;
        const int m00 = h * 8 + w;
        const float v = w00 * Cs[m00 * 56 + ij]
                      + w01 * Cs[(m00 + 1) * 56 + ij]
                      + w10 * Cs[(m00 + 8) * 56 + ij]
                      + w11 * Cs[(m00 + 9) * 56 + ij];
        vrow[idx] = tf32r(v);
    }
}

// ---------------- 3-stage tf32 GEMM, 128x128 tile, 4 warps of 64x64,
// register-double-buffered fragments ------------------------------------
__device__ __forceinline__ float gelu_exact(float v)
{
    return 0.5f * v * (1.f + erff(v * 0.7071067811865475f));
}

#define AST 20   // A smem word stride per m row (16 k + pad)
#define BST 136  // B smem word stride per k row (128 n + pad)
#define STG_A (128 * AST)   // 2560 words
#define STG_B (16 * BST)    // 2176 words
#define GEMM_SMEM (3 * (STG_A + STG_B) * 4)   // 56832 B

template <bool GELU, bool ROUND_OUT>
__global__ __launch_bounds__(128, 2)
void tf32_gemm_pipe(const float* __restrict__ A, int lda,
                    const float* __restrict__ B, int ldb,
                    const float* __restrict__ bias,
                    float* __restrict__ C, int ldc,
                    int K, int Kvalid)
{
    extern __shared__ float smg[];
    float* AsBase = smg;                    // 3 x STG_A
    float* BsBase = smg + 3 * STG_A;        // 3 x STG_B

    const int tid  = threadIdx.x;
    const int lane = tid & 31;
    const int warp = tid >> 5;              // 0..3
    const int m0 = blockIdx.y * 128, n0 = blockIdx.x * 128;
    const int wm = (warp >> 1) * 64, wn = (warp & 1) * 64;
    const int t = lane & 3, g = lane >> 2;

    // staging assignments (128 threads)
    const int am  = tid;
    const int bk0 = tid >> 5;               // 0..3
    const int bnc = (tid & 31) * 4;

    uint32_t sA[3], sB[3];
    {
        uint32_t a = (uint32_t)__cvta_generic_to_shared(AsBase);
        uint32_t b = (uint32_t)__cvta_generic_to_shared(BsBase);
        #pragma unroll
        for (int st = 0; st < 3; st++) {
            sA[st] = a + (st * STG_A + am * AST) * 4;
            sB[st] = b + (st * STG_B + bk0 * BST + bnc) * 4;
        }
    }
    const float* gA = A + (size_t)(m0 + am) * lda;
    const float* gB = B + (size_t)bk0 * ldb + n0 + bnc;

    const int NIT = K / 16;

    auto prefetch = [&](int it, int st) {
        const int k0 = it * 16;
        #pragma unroll
        for (int q = 0; q < 4; q++)
            cpa16(sA[st] + q * 16, gA + k0 + q * 4, true);
        #pragma unroll
        for (int q = 0; q < 4; q++)
            cpa16(sB[st] + q * 4 * BST * 4,
                  gB + (size_t)(k0 + q * 4) * ldb,
                  k0 + bk0 + q * 4 < Kvalid);
        cpa_commit();
    };

    auto ldfrag = [&](const float* Ab, const float* Bb, int kb,
                      uint32_t af[4][4], uint32_t bf[8][2]) {
        #pragma unroll
        for (int mi = 0; mi < 4; mi++) {
            const int r = (wm + mi * 16 + g) * AST + kb + t;
            af[mi][0] = __float_as_uint(Ab[r]);
            af[mi][1] = __float_as_uint(Ab[r + 8 * AST]);
            af[mi][2] = __float_as_uint(Ab[r + 4]);
            af[mi][3] = __float_as_uint(Ab[r + 8 * AST + 4]);
        }
        #pragma unroll
        for (int ni = 0; ni < 8; ni++) {
            const int cidx = (kb + t) * BST + wn + ni * 8 + g;
            bf[ni][0] = __float_as_uint(Bb[cidx]);
            bf[ni][1] = __float_as_uint(Bb[cidx + 4 * BST]);
        }
    };

    float acc[4][8][4];
    #pragma unroll
    for (int mi = 0; mi < 4; mi++)
        #pragma unroll
        for (int ni = 0; ni < 8; ni++)
            #pragma unroll
            for (int q = 0; q < 4; q++) acc[mi][ni][q] = 0.f;

    auto dommas = [&](uint32_t af[4][4], uint32_t bf[8][2]) {
        #pragma unroll
        for (int mi = 0; mi < 4; mi++)
            #pragma unroll
            for (int ni = 0; ni < 8; ni++)
                mma_tf32(acc[mi][ni], af[mi], bf[ni]);
    };

    prefetch(0, 0);
    if (1 < NIT) prefetch(1, 1);

    uint32_t afA[4][4], bfA[8][2], afB[4][4], bfB[8][2];
    bool first = true;

    for (int it = 0; it < NIT; it++) {
        const int st = it % 3;
        if (it + 2 < NIT) {
            prefetch(it + 2, (it + 2) % 3);
            cpa_wait1();   // stages it AND it+1 complete; only it+2 in flight
        } else {
            cpa_wait0();
        }
        __syncthreads();   // stages it and it+1 visible to all threads

        const float* Ab = AsBase + st * STG_A;
        const float* Bb = BsBase + st * STG_B;
        if (first) { ldfrag(Ab, Bb, 0, afA, bfA); first = false; }
        ldfrag(Ab, Bb, 8, afB, bfB);   // kb=8 loads fly under kb=0 MMAs
        dommas(afA, bfA);
        if (it + 1 < NIT) {            // preload next stage's kb=0 under kb=8 MMAs
            const int stn = (it + 1) % 3;
            ldfrag(AsBase + stn * STG_A, BsBase + stn * STG_B, 0, afA, bfA);
        }
        dommas(afB, bfB);
        __syncthreads();   // all warps done with stage st before it is refilled
    }

    // epilogue: bias (+gelu) (+tf32 round), write C
    #pragma unroll
    for (int mi = 0; mi < 4; mi++) {
        const int r0 = m0 + wm + mi * 16 + g;
        #pragma unroll
        for (int ni = 0; ni < 8; ni++) {
            const int c0 = n0 + wn + ni * 8 + 2 * t;
            const float bb0 = bias[c0], bb1 = bias[c0 + 1];
            float v0 = acc[mi][ni][0] + bb0;
            float v1 = acc[mi][ni][1] + bb1;
            float v2 = acc[mi][ni][2] + bb0;
            float v3 = acc[mi][ni][3] + bb1;
            if (GELU) {
                v0 = gelu_exact(v0); v1 = gelu_exact(v1);
                v2 = gelu_exact(v2); v3 = gelu_exact(v3);
            }
            if (ROUND_OUT) {
                v0 = tf32r(v0); v1 = tf32r(v1);
                v2 = tf32r(v2); v3 = tf32r(v3);
            }
            *(float2*)(C + (size_t)r0 * ldc + c0)       = make_float2(v0, v1);
            *(float2*)(C + (size_t)(r0 + 8) * ldc + c0) = make_float2(v2, v3);
        }
    }
}

// ---------------- final assembly: concat + posenc + time embedding ----------------
__global__ void assemble_kernel(const float* __restrict__ emb,
                                const float* __restrict__ coords,
                                const float* __restrict__ vis,
                                const float* __restrict__ conf,
                                float* __restrict__ out)
{
    const int n = blockIdx.x, s = blockIdx.y;
    const int sn = s * N_ + n;

    float rfx = 0.f, rfy = 0.f, rbx = 0.f, rby = 0.f;
    const float cx = coords[sn * 2], cy = coords[sn * 2 + 1];
    if (s < S_ - 1) {
        rfx = cx - coords[((s + 1) * N_ + n) * 2];
        rfy = cy - coords[((s + 1) * N_ + n) * 2 + 1];
    }
    if (s > 0) {
        rbx = cx - coords[((s - 1) * N_ + n) * 2];
        rby = cy - coords[((s - 1) * N_ + n) * 2 + 1];
    }
    float p4[4];
    p4[0] = rfx / 64.f;
    p4[1] = rfy / 48.f;
    p4[2] = rbx / 64.f;
    p4[3] = rby / 48.f;

    float* orow = out + (size_t)(n * S_ + s) * 854;
    for (int f = threadIdx.x; f < 854; f += 256) {
        float v;
        if (f == 0)      v = vis[sn];
        else if (f == 1) v = conf[sn];
        else if (f < 770) {
            const int lev = (f - 2) >> 8;
            const int c   = (f - 2) & 255;
            v = emb[((size_t)(lev * 4096 + sn)) * 256 + c];
        } else {
            const int j = f - 770;
            if (j < 4) v = p4[j];
            else if (j < 44) {
                const int i = (j - 4) >> 2, q = (j - 4) & 3;
                v = sinf(exp2f((float)i) * p4[q]);
            } else {
                const int i = (j - 44) >> 2, q = (j - 44) & 3;
                v = sinf(exp2f((float)i) * p4[q] + 1.5707963267948966f);
            }
        }
        const int i2 = (f < 427) ? f : f - 427;
        const float omega = expf(-9.210340371976184f * (float)i2 / 427.0f);
        const float ang = (float)s * omega;
        v += (f < 427) ? sinf(ang) : cosf(ang);
        orow[f] = v;
    }
}

// ---------------- launch ----------------
extern "C" void kernel_launch(void* const* d_in, const int* in_sizes, int n_in,
                              void* d_out, int out_size)
{
    (void)in_sizes; (void)n_in; (void)out_size;
    const float* fm0    = (const float*)d_in[0];
    const float* fm1    = (const float*)d_in[1];
    const float* fm2    = (const float*)d_in[2];
    const float* coords = (const float*)d_in[3];
    const float* tf0    = (const float*)d_in[4];
    const float* tf1    = (const float*)d_in[5];
    const float* tf2    = (const float*)d_in[6];
    const float* vis    = (const float*)d_in[7];
    const float* conf   = (const float*)d_in[8];
    const float* W1     = (const float*)d_in[9];
    const float* b1     = (const float*)d_in[10];
    const float* W2     = (const float*)d_in[11];
    const float* W2b    = (const float*)d_in[12];
    float* out = (float*)d_out;

    float *fT, *vol, *hbuf, *ebuf, *w1r, *w2r;
    cudaGetSymbolAddress((void**)&fT,   g_fmapT);
    cudaGetSymbolAddress((void**)&vol,  g_vol);
    cudaGetSymbolAddress((void**)&hbuf, g_h);
    cudaGetSymbolAddress((void**)&ebuf, g_emb);
    cudaGetSymbolAddress((void**)&w1r,  g_w1r);
    cudaGetSymbolAddress((void**)&w2r,  g_w2r);

    cudaFuncSetAttribute(vol_kernel, cudaFuncAttributeMaxDynamicSharedMemorySize, VOL_SMEM);
    cudaFuncSetAttribute(tf32_gemm_pipe<true,  true >, cudaFuncAttributeMaxDynamicSharedMemorySize, GEMM_SMEM);
    cudaFuncSetAttribute(tf32_gemm_pipe<false, false>, cudaFuncAttributeMaxDynamicSharedMemorySize, GEMM_SMEM);

    // launch order puts gemm1 at profiled slot #4
    transpose_all_kernel<<<dim3(126, 4, 16), dim3(32, 8)>>>(fm0, fm1, fm2, fT);

    const int NR = K1 * 384 + 384 * 256;
    round2_kernel<<<(NR + 255) / 256, 256>>>(W1, w1r, K1 * 384, W2, w2r, 384 * 256);

    vol_kernel<<<dim3(N_, S_, 3), 256, VOL_SMEM>>>(fT, tf0, tf1, tf2, coords, vol);

    tf32_gemm_pipe<true,  true ><<<dim3(3, 96), 128, GEMM_SMEM>>>(vol,  VSTR, w1r, 384, b1,  hbuf, 384, VSTR, K1);
    tf32_gemm_pipe<false, false><<<dim3(2, 96), 128, GEMM_SMEM>>>(hbuf, 384,  w2r, 256, W2b, ebuf, 256, 384,  384);

    assemble_kernel<<<dim3(N_, S_), 256>>>(ebuf, coords, vis, conf, out);
}